// round 3
// baseline (speedup 1.0000x reference)
#include <cuda_runtime.h>

// NeRF fine sampling:
//   inputs : rays_o [N,3], rays_d [N,3], z_vals [N,64] (sorted), weights [N,64]
//   outputs: pts [N,192,3], z_all [N,192]   (concatenated in d_out: pts first)
//
// One warp per ray. All intermediates staged in shared memory.

#define NS        64      // coarse samples
#define NI        128     // importance samples
#define NALL      192     // NS + NI
#define RPB       8       // rays per block (8 warps)
#define FULLMASK  0xffffffffu

__global__ __launch_bounds__(256, 8)
void nerf_fine_sample_kernel(
    const float* __restrict__ rays_o,
    const float* __restrict__ rays_d,
    const float* __restrict__ z_vals,
    const float* __restrict__ weights,
    float* __restrict__ out_pts,   // [N,192,3]
    float* __restrict__ out_z,     // [N,192] (may be null if out buffer too small)
    int n_rays,
    int write_pts,                 // bounds guards derived from out_size
    int write_z)
{
    // per-warp layout (512 floats): z[0..63], mid[64..127] (63 used),
    // cdf[128..191] (63 used), samp[192..319], all[320..511]
    __shared__ float smem[RPB][512];

    const int warp = threadIdx.x >> 5;
    const int lane = threadIdx.x & 31;
    const int ray  = blockIdx.x * RPB + warp;
    if (ray >= n_rays) return;

    float* s_z    = smem[warp];
    float* s_mid  = s_z + 64;
    float* s_cdf  = s_z + 128;
    float* s_samp = s_z + 192;
    float* s_all  = s_z + 320;

    // ---- load z_vals, compute mids -------------------------------------
    const float* zr = z_vals + (size_t)ray * NS;
    s_z[lane]      = zr[lane];
    s_z[lane + 32] = zr[lane + 32];
    __syncwarp();

    s_mid[lane] = 0.5f * (s_z[lane] + s_z[lane + 1]);
    if (lane < 31)
        s_mid[lane + 32] = 0.5f * (s_z[lane + 32] + s_z[lane + 33]);

    // ---- weights -> pdf -> cdf (warp inclusive scan over 62 values) ----
    const float* wr = weights + (size_t)ray * NS;
    float a = wr[1 + lane] + 1e-5f;                              // w[0..31]
    float b = (lane < 30) ? (wr[33 + lane] + 1e-5f) : 0.0f;      // w[32..61]

    #pragma unroll
    for (int off = 1; off < 32; off <<= 1) {
        float v = __shfl_up_sync(FULLMASK, a, off);
        if (lane >= off) a += v;
    }
    float totA = __shfl_sync(FULLMASK, a, 31);
    #pragma unroll
    for (int off = 1; off < 32; off <<= 1) {
        float v = __shfl_up_sync(FULLMASK, b, off);
        if (lane >= off) b += v;
    }
    b += totA;
    const float wsum = __shfl_sync(FULLMASK, b, 31);  // total (tail lanes add 0)
    const float inv  = 1.0f / wsum;

    // cdf has 63 entries: cdf[0]=0, cdf[k]=prefix(pdf[0..k-1])
    if (lane == 0) s_cdf[0] = 0.0f;
    s_cdf[lane + 1] = a * inv;                 // cdf[1..32]
    if (lane < 30) s_cdf[lane + 33] = b * inv; // cdf[33..62]
    __syncwarp();

    // ---- inverse-CDF sampling: 4 samples per lane ----------------------
    #pragma unroll
    for (int t = 0; t < 4; t++) {
        const int   s = lane + 32 * t;
        const float u = (float)s * (1.0f / 127.0f);

        // searchsorted(cdf, u, side='right'): first index with cdf > u
        int lo = 0, hi = 63;
        while (lo < hi) {
            int m = (lo + hi) >> 1;
            if (s_cdf[m] <= u) lo = m + 1; else hi = m;
        }
        const int below = max(lo - 1, 0);
        const int above = min(lo, 62);

        const float cb = s_cdf[below], ca = s_cdf[above];
        const float bb = s_mid[below], ba = s_mid[above];
        float den = ca - cb;
        den = (den < 1e-5f) ? 1.0f : den;
        const float tt = (u - cb) / den;
        s_samp[s] = bb + tt * (ba - bb);
    }
    __syncwarp();

    // ---- merge two sorted lists ---------------------------------------
    // z_vals element i -> rank i + #{samp < z}
    #pragma unroll
    for (int t = 0; t < 2; t++) {
        const int   i = lane + 32 * t;
        const float v = s_z[i];
        int lo = 0, hi = NI;
        while (lo < hi) {
            int m = (lo + hi) >> 1;
            if (s_samp[m] < v) lo = m + 1; else hi = m;
        }
        s_all[i + lo] = v;
    }
    // samples element j -> rank j + #{z <= samp}
    #pragma unroll
    for (int t = 0; t < 4; t++) {
        const int   j = lane + 32 * t;
        const float v = s_samp[j];
        int lo = 0, hi = NS;
        while (lo < hi) {
            int m = (lo + hi) >> 1;
            if (s_z[m] <= v) lo = m + 1; else hi = m;
        }
        s_all[j + lo] = v;
    }
    __syncwarp();

    // ---- outputs (streaming stores: write-once data) -------------------
    const float ox = rays_o[ray * 3 + 0];
    const float oy = rays_o[ray * 3 + 1];
    const float oz = rays_o[ray * 3 + 2];
    const float dx = rays_d[ray * 3 + 0];
    const float dy = rays_d[ray * 3 + 1];
    const float dz = rays_d[ray * 3 + 2];

    if (write_pts) {
        float* po = out_pts + (size_t)ray * (NALL * 3);
        #pragma unroll
        for (int t = 0; t < 18; t++) {          // 576 floats, coalesced
            const int e = lane + 32 * t;
            const int s = e / 3;
            const int c = e - 3 * s;
            const float zv = s_all[s];
            const float o = (c == 0) ? ox : ((c == 1) ? oy : oz);
            const float d = (c == 0) ? dx : ((c == 1) ? dy : dz);
            __stcs(po + e, fmaf(d, zv, o));
        }
    }

    if (write_z) {
        float* zo = out_z + (size_t)ray * NALL;
        #pragma unroll
        for (int t = 0; t < 6; t++)             // 192 floats, coalesced
            __stcs(zo + lane + 32 * t, s_all[lane + 32 * t]);
    }
}

extern "C" void kernel_launch(void* const* d_in, const int* in_sizes, int n_in,
                              void* d_out, int out_size)
{
    const float* rays_o  = (const float*)d_in[0];
    const float* rays_d  = (const float*)d_in[1];
    const float* z_vals  = (const float*)d_in[2];
    const float* weights = (const float*)d_in[3];

    const int n_rays = in_sizes[0] / 3;

    // Expected: out = [pts (N*192*3 floats) | z_all (N*192 floats)]
    const long long pts_elems = (long long)n_rays * NALL * 3;
    const long long z_elems   = (long long)n_rays * NALL;

    const int write_pts = (out_size >= pts_elems) ? 1 : 0;
    const int write_z   = (out_size >= pts_elems + z_elems) ? 1 : 0;

    float* out_pts = (float*)d_out;
    float* out_z   = out_pts + pts_elems;

    dim3 grid((n_rays + RPB - 1) / RPB);
    nerf_fine_sample_kernel<<<grid, 256>>>(
        rays_o, rays_d, z_vals, weights, out_pts, out_z, n_rays,
        write_pts, write_z);
}

// round 4
// speedup vs baseline: 1.4897x; 1.4897x over previous
#include <cuda_runtime.h>

// NeRF fine sampling:
//   inputs : rays_o [N,3], rays_d [N,3], z_vals [N,64] (sorted), weights [N,64]
//   outputs: pts [N,192,3], z_all [N,192]   (concatenated in d_out: pts first)
// One warp per ray. Branchless searches, float4 stores.

#define NS        64
#define NI        128
#define NALL      192
#define RPB       8
#define FULLMASK  0xffffffffu

// count of a[0..63] <= v  (result in [0,64]; with a[63]=+INF sentinel, <=63)
__device__ __forceinline__ int cnt_le_64(const float* __restrict__ a, float v) {
    int pos = 0;
    #pragma unroll
    for (int step = 32; step >= 1; step >>= 1)
        if (a[pos + step - 1] <= v) pos += step;
    if (a[pos] <= v) pos++;
    return pos;
}

// count of a[0..127] < v  (result in [0,128])
__device__ __forceinline__ int cnt_lt_128(const float* __restrict__ a, float v) {
    int pos = 0;
    #pragma unroll
    for (int step = 64; step >= 1; step >>= 1)
        if (a[pos + step - 1] < v) pos += step;
    if (a[pos] < v) pos++;
    return pos;
}

__global__ __launch_bounds__(256, 8)
void nerf_fine_sample_kernel(
    const float* __restrict__ rays_o,
    const float* __restrict__ rays_d,
    const float* __restrict__ z_vals,
    const float* __restrict__ weights,
    float* __restrict__ out_pts,   // [N,192,3]
    float* __restrict__ out_z,     // [N,192]
    int n_rays,
    int write_pts,
    int write_z)
{
    // per-warp (512 floats): z[0..63], mid[64..127], cdf[128..191] (64 w/ INF),
    // samp[192..319], all[320..511]
    __shared__ float smem[RPB][512];

    const int warp = threadIdx.x >> 5;
    const int lane = threadIdx.x & 31;
    const int ray  = blockIdx.x * RPB + warp;
    if (ray >= n_rays) return;

    float* s_z    = smem[warp];
    float* s_mid  = s_z + 64;
    float* s_cdf  = s_z + 128;
    float* s_samp = s_z + 192;
    float* s_all  = s_z + 320;

    // ---- load z_vals, compute mids -------------------------------------
    const float* zr = z_vals + (size_t)ray * NS;
    s_z[lane]      = zr[lane];
    s_z[lane + 32] = zr[lane + 32];
    __syncwarp();

    s_mid[lane] = 0.5f * (s_z[lane] + s_z[lane + 1]);
    if (lane < 31)
        s_mid[lane + 32] = 0.5f * (s_z[lane + 32] + s_z[lane + 33]);

    // ---- weights -> pdf -> cdf (warp inclusive scan over 62 values) ----
    const float* wr = weights + (size_t)ray * NS;
    float a = wr[1 + lane] + 1e-5f;                              // w[0..31]
    float b = (lane < 30) ? (wr[33 + lane] + 1e-5f) : 0.0f;      // w[32..61]

    #pragma unroll
    for (int off = 1; off < 32; off <<= 1) {
        float v = __shfl_up_sync(FULLMASK, a, off);
        if (lane >= off) a += v;
    }
    float totA = __shfl_sync(FULLMASK, a, 31);
    #pragma unroll
    for (int off = 1; off < 32; off <<= 1) {
        float v = __shfl_up_sync(FULLMASK, b, off);
        if (lane >= off) b += v;
    }
    b += totA;
    const float wsum = __shfl_sync(FULLMASK, b, 31);
    const float inv  = 1.0f / wsum;

    // cdf[0..62] real, cdf[63] = +INF sentinel
    if (lane == 0) s_cdf[0] = 0.0f;
    if (lane == 31) s_cdf[63] = __int_as_float(0x7f800000);  // +INF
    s_cdf[lane + 1] = a * inv;                 // cdf[1..32]
    if (lane < 30) s_cdf[lane + 33] = b * inv; // cdf[33..62]
    __syncwarp();

    // ---- inverse-CDF sampling: 4 samples per lane (branchless search) --
    #pragma unroll
    for (int t = 0; t < 4; t++) {
        const int   s = lane + 32 * t;
        const float u = (float)s * (1.0f / 127.0f);

        const int ind   = cnt_le_64(s_cdf, u);   // searchsorted right
        const int below = max(ind - 1, 0);
        const int above = min(ind, 62);

        const float cb = s_cdf[below], ca = s_cdf[above];
        const float bb = s_mid[below], ba = s_mid[above];
        float den = ca - cb;
        den = (den < 1e-5f) ? 1.0f : den;
        const float tt = (u - cb) / den;
        s_samp[s] = bb + tt * (ba - bb);
    }
    __syncwarp();

    // ---- stable merge of two sorted lists (branchless rank search) ----
    #pragma unroll
    for (int t = 0; t < 2; t++) {
        const int   i = lane + 32 * t;
        const float v = s_z[i];
        s_all[i + cnt_lt_128(s_samp, v)] = v;    // rank = i + #{samp < v}
    }
    #pragma unroll
    for (int t = 0; t < 4; t++) {
        const int   j = lane + 32 * t;
        const float v = s_samp[j];
        s_all[j + cnt_le_64(s_z, v)] = v;        // rank = j + #{z <= v}
    }
    __syncwarp();

    // ---- outputs: vectorized float4 streaming stores -------------------
    const float ox = rays_o[ray * 3 + 0];
    const float oy = rays_o[ray * 3 + 1];
    const float oz = rays_o[ray * 3 + 2];
    const float dx = rays_d[ray * 3 + 0];
    const float dy = rays_d[ray * 3 + 1];
    const float dz = rays_d[ray * 3 + 2];

    if (write_pts) {
        // 576 floats = 144 float4 per ray; ray offset 2304B -> 16B aligned
        float4* po4 = (float4*)(out_pts + (size_t)ray * (NALL * 3));
        #pragma unroll
        for (int t = 0; t < 5; t++) {
            const int p = lane + 32 * t;         // float4 index
            if (t < 4 || lane < 16) {            // p < 144
                const int e0 = 4 * p;
                const int s0 = e0 / 3;           // first sample covered
                const int r  = e0 - 3 * s0;      // phase 0/1/2
                const float z0 = s_all[s0];
                const float z1 = s_all[s0 + 1];
                const float p0x = fmaf(dx, z0, ox);
                const float p0y = fmaf(dy, z0, oy);
                const float p0z = fmaf(dz, z0, oz);
                const float p1x = fmaf(dx, z1, ox);
                const float p1y = fmaf(dy, z1, oy);
                const float p1z = fmaf(dz, z1, oz);
                float4 v;
                // r=0: (p0x p0y p0z p1x)  r=1: (p0y p0z p1x p1y)  r=2: (p0z p1x p1y p1z)
                v.x = (r == 0) ? p0x : ((r == 1) ? p0y : p0z);
                v.y = (r == 0) ? p0y : ((r == 1) ? p0z : p1x);
                v.z = (r == 0) ? p0z : ((r == 1) ? p1x : p1y);
                v.w = (r == 0) ? p1x : ((r == 1) ? p1y : p1z);
                __stcs(po4 + p, v);
            }
        }
    }

    if (write_z) {
        // 192 floats = 48 float4; s_all offset 1280B -> LDS.128-aligned
        float4* zo4 = (float4*)(out_z + (size_t)ray * NALL);
        const float4* sa4 = (const float4*)s_all;
        #pragma unroll
        for (int t = 0; t < 2; t++) {
            const int q = lane + 32 * t;
            if (t == 0 || lane < 16)             // q < 48
                __stcs(zo4 + q, sa4[q]);
        }
    }
}

extern "C" void kernel_launch(void* const* d_in, const int* in_sizes, int n_in,
                              void* d_out, int out_size)
{
    const float* rays_o  = (const float*)d_in[0];
    const float* rays_d  = (const float*)d_in[1];
    const float* z_vals  = (const float*)d_in[2];
    const float* weights = (const float*)d_in[3];

    const int n_rays = in_sizes[0] / 3;

    const long long pts_elems = (long long)n_rays * NALL * 3;
    const long long z_elems   = (long long)n_rays * NALL;

    const int write_pts = (out_size >= pts_elems) ? 1 : 0;
    const int write_z   = (out_size >= pts_elems + z_elems) ? 1 : 0;

    float* out_pts = (float*)d_out;
    float* out_z   = out_pts + pts_elems;

    dim3 grid((n_rays + RPB - 1) / RPB);
    nerf_fine_sample_kernel<<<grid, 256>>>(
        rays_o, rays_d, z_vals, weights, out_pts, out_z, n_rays,
        write_pts, write_z);
}